// round 4
// baseline (speedup 1.0000x reference)
#include <cuda_runtime.h>
#include <cstdint>

typedef unsigned long long ull;

#define B_T    16000      // B*T rows
#define D_IN   320
#define E_DIM  16
#define K_CB   8192
#define KSPLIT 8
#define KSEG   (K_CB / KSPLIT)        // 1024 candidates per segment
#define CHUNK  512                    // candidates staged in smem per pass
#define NCHUNK (KSEG / CHUNK)         // 2
#define ROWS_PB 64                    // rows per block (32 lanes * 2 rows/thread)
#define NBLK_ROWS (B_T / ROWS_PB)     // 250
#define T2     256

// ---- scratch (device globals are the sanctioned no-alloc path) ----
__device__ float g_V[B_T * E_DIM];
__device__ float g_pv[KSPLIT * B_T];
__device__ int   g_pi[KSPLIT * B_T];

// ---- packed f32x2 helpers (FFMA2 only reachable via PTX fma.rn.f32x2) ----
__device__ __forceinline__ ull pack2same(float x) {
    ull r; asm("mov.b64 %0, {%1, %1};" : "=l"(r) : "f"(x)); return r;
}
__device__ __forceinline__ void unpack2(ull v, float& lo, float& hi) {
    asm("mov.b64 {%0, %1}, %2;" : "=f"(lo), "=f"(hi) : "l"(v));
}
__device__ __forceinline__ ull ffma2(ull a, ull b, ull c) {
    ull d; asm("fma.rn.f32x2 %0, %1, %2, %3;" : "=l"(d) : "l"(a), "l"(b), "l"(c)); return d;
}
__device__ __forceinline__ ull fmul2(ull a, ull b) {
    ull d; asm("mul.rn.f32x2 %0, %1, %2;" : "=l"(d) : "l"(a), "l"(b)); return d;
}
__device__ __forceinline__ ull fadd2(ull a, ull b) {
    ull d; asm("add.rn.f32x2 %0, %1, %2;" : "=l"(d) : "l"(a), "l"(b)); return d;
}

// ============================================================================
// Kernel 1: V = H * P.  4 threads per row (80 d's each), shfl-bfly reduce.
// 250 blocks x 256 threads -> 64K threads (4x round-3), f32x2 accumulators.
// ============================================================================
__global__ __launch_bounds__(256) void proj_kernel(const float* __restrict__ H,
                                                   const float* __restrict__ P) {
    __shared__ __align__(16) ull Ps[D_IN * E_DIM / 2];   // 20 KB, packed e-pairs
    {
        const ull* Pg = (const ull*)P;
        for (int i = threadIdx.x; i < D_IN * E_DIM / 2; i += 256) Ps[i] = Pg[i];
    }
    __syncthreads();

    const int tid = threadIdx.x;
    const int row = blockIdx.x * 64 + (tid >> 2);       // 64 rows / block
    const int seg = tid & 3;                            // 4 d-segments / row

    ull acc[8];
#pragma unroll
    for (int j = 0; j < 8; ++j) acc[j] = 0ULL;

    const float4* h4 = (const float4*)(H + (size_t)row * D_IN + seg * 80);
#pragma unroll 4
    for (int i = 0; i < 20; ++i) {                      // 20 float4 = 80 d's
        float4 h = h4[i];
        const int d = seg * 80 + i * 4;
        ull hx = pack2same(h.x), hy = pack2same(h.y);
        ull hz = pack2same(h.z), hw = pack2same(h.w);
        const ull* p = &Ps[d * 8];
#pragma unroll
        for (int j = 0; j < 8; ++j) {
            ull a = acc[j];
            a = ffma2(p[j],      hx, a);
            a = ffma2(p[8 + j],  hy, a);
            a = ffma2(p[16 + j], hz, a);
            a = ffma2(p[24 + j], hw, a);
            acc[j] = a;
        }
    }

    // reduce across the 4 segment lanes (xor 1, xor 2)
#pragma unroll
    for (int j = 0; j < 8; ++j) {
        acc[j] = fadd2(acc[j], __shfl_xor_sync(0xFFFFFFFFu, acc[j], 1));
        acc[j] = fadd2(acc[j], __shfl_xor_sync(0xFFFFFFFFu, acc[j], 2));
    }

    // each of the 4 lanes writes its quarter (2 ulls = 16B) of the row
    ull* vout = (ull*)(g_V + (size_t)row * E_DIM);
    vout[2 * seg]     = acc[2 * seg];
    vout[2 * seg + 1] = acc[2 * seg + 1];
}

// ============================================================================
// Kernel 2: fused scores + argmax over one K segment, f32x2 math.
// grid = (250 row-groups, 8 ksegs). 8 warps; lanes = 32 rows, 2 rows/thread.
// CB chunk (512 cands, 32 KB) in smem; all lanes of a warp read the SAME
// candidate row -> pure LDS.128 broadcast.
// ============================================================================
__device__ __forceinline__ float dot16p(ull c0, ull c1, ull c2, ull c3,
                                        ull c4, ull c5, ull c6, ull c7,
                                        const ull* __restrict__ v) {
    ull a = fmul2(c0, v[0]);
    a = ffma2(c1, v[1], a);
    a = ffma2(c2, v[2], a);
    a = ffma2(c3, v[3], a);
    a = ffma2(c4, v[4], a);
    a = ffma2(c5, v[5], a);
    a = ffma2(c6, v[6], a);
    a = ffma2(c7, v[7], a);
    float lo, hi; unpack2(a, lo, hi);
    return lo + hi;
}

__global__ __launch_bounds__(T2) void score_kernel(const float* __restrict__ CB) {
    __shared__ __align__(16) ull cb_s[CHUNK * 8];       // 32 KB
    __shared__ float  red_v[8][ROWS_PB];                // 2 KB
    __shared__ int    red_i[8][ROWS_PB];                // 2 KB

    const int tid  = threadIdx.x;
    const int lane = tid & 31;
    const int warp = tid >> 5;
    const int row_base = blockIdx.x * ROWS_PB;
    const int kseg = blockIdx.y;

    // this thread's two row vectors (16 floats = 8 packed pairs each)
    ull v0[8], v1[8];
    {
        const ulonglong2* V0 = (const ulonglong2*)(g_V + (size_t)(row_base + lane) * E_DIM);
        const ulonglong2* V1 = (const ulonglong2*)(g_V + (size_t)(row_base + 32 + lane) * E_DIM);
#pragma unroll
        for (int j = 0; j < 4; ++j) {
            ulonglong2 a = V0[j]; v0[2 * j] = a.x; v0[2 * j + 1] = a.y;
            ulonglong2 b = V1[j]; v1[2 * j] = b.x; v1[2 * j + 1] = b.y;
        }
    }

    float best0 = __int_as_float(0xff800000);   // -inf
    float best1 = __int_as_float(0xff800000);
    int bi0 = 0, bi1 = 0;

    const float4* cbg = (const float4*)CB;
    for (int c = 0; c < NCHUNK; ++c) {
        __syncthreads();
        {   // stage chunk: 512 cands * 64 B = 2048 float4
            const float4* src = cbg + ((size_t)kseg * KSEG + (size_t)c * CHUNK) * 4;
            float4* dst = (float4*)cb_s;
#pragma unroll
            for (int i = 0; i < (CHUNK * 4) / T2; ++i)
                dst[tid + i * T2] = src[tid + i * T2];
        }
        __syncthreads();

        const int jbase = warp * (CHUNK / 8);               // 64-cand stripe / warp
        const int kbase = kseg * KSEG + c * CHUNK + jbase;
#pragma unroll 4
        for (int j = 0; j < CHUNK / 8; ++j) {
            const ulonglong2* q = (const ulonglong2*)(cb_s + (size_t)(jbase + j) * 8);
            ulonglong2 t0 = q[0], t1 = q[1], t2 = q[2], t3 = q[3];
            float s0 = dot16p(t0.x, t0.y, t1.x, t1.y, t2.x, t2.y, t3.x, t3.y, v0);
            float s1 = dot16p(t0.x, t0.y, t1.x, t1.y, t2.x, t2.y, t3.x, t3.y, v1);
            int k = kbase + j;
            if (s0 > best0) { best0 = s0; bi0 = k; }        // strict > == first-max
            if (s1 > best1) { best1 = s1; bi1 = k; }
        }
    }

    // cross-warp reduce (warps hold disjoint k-stripes of the same 64 rows)
    red_v[warp][lane]      = best0;  red_i[warp][lane]      = bi0;
    red_v[warp][32 + lane] = best1;  red_i[warp][32 + lane] = bi1;
    __syncthreads();
    if (tid < ROWS_PB) {
        float bv = red_v[0][tid]; int bi = red_i[0][tid];
#pragma unroll
        for (int w = 1; w < 8; ++w) {
            float v = red_v[w][tid]; int i = red_i[w][tid];
            if (v > bv || (v == bv && i < bi)) { bv = v; bi = i; }
        }
        g_pv[(size_t)kseg * B_T + row_base + tid] = bv;
        g_pi[(size_t)kseg * B_T + row_base + tid] = bi;
    }
}

// ============================================================================
// Kernel 3: combine KSPLIT partials; output label as float VALUE (output dtype
// is float32 -- int bit patterns read as denormals, the round-1/2 bug).
// ============================================================================
__global__ __launch_bounds__(256) void combine_kernel(float* __restrict__ out) {
    int row = blockIdx.x * 256 + threadIdx.x;
    if (row >= B_T) return;
    float bv = g_pv[row];
    int   bi = g_pi[row];
#pragma unroll
    for (int s = 1; s < KSPLIT; ++s) {
        float v = g_pv[(size_t)s * B_T + row];
        int   i = g_pi[(size_t)s * B_T + row];
        if (v > bv || (v == bv && i < bi)) { bv = v; bi = i; }
    }
    out[row] = (float)bi;
}

// ============================================================================
extern "C" void kernel_launch(void* const* d_in, const int* in_sizes, int n_in,
                              void* d_out, int out_size) {
    // Input dispatch by element count (ordering-proof):
    //   H  = 16000*320 = 5,120,000 ; P = 320*16 = 5,120 ; CB = 8192*16 = 131,072
    const float* H  = nullptr;
    const float* P  = nullptr;
    const float* CB = nullptr;
    for (int i = 0; i < n_in; ++i) {
        if      (in_sizes[i] == B_T * D_IN)   H  = (const float*)d_in[i];
        else if (in_sizes[i] == D_IN * E_DIM) P  = (const float*)d_in[i];
        else if (in_sizes[i] == K_CB * E_DIM) CB = (const float*)d_in[i];
    }
    if (!H)  H  = (const float*)d_in[0];
    if (!P)  P  = (const float*)d_in[1];
    if (!CB) CB = (const float*)d_in[2];

    float* out = (float*)d_out;

    proj_kernel<<<NBLK_ROWS, 256>>>(H, P);
    score_kernel<<<dim3(NBLK_ROWS, KSPLIT), T2>>>(CB);
    combine_kernel<<<(B_T + 255) / 256, 256>>>(out);
}

// round 5
// speedup vs baseline: 1.0466x; 1.0466x over previous
#include <cuda_runtime.h>
#include <cstdint>

typedef unsigned long long ull;

#define B_T    16000      // B*T rows
#define D_IN   320
#define E_DIM  16
#define K_CB   8192
#define KSPLIT 16
#define KSEG   (K_CB / KSPLIT)        // 512 candidates per segment = one smem chunk
#define ROWS_PB 128                   // rows per block (32 lanes * 4 rows/thread)
#define NBLK_ROWS (B_T / ROWS_PB)     // 125
#define T2     256

// ---- scratch (device globals are the sanctioned no-alloc path) ----
__device__ float g_V[B_T * E_DIM];
__device__ float g_pv[KSPLIT * B_T];
__device__ int   g_pi[KSPLIT * B_T];

// ---- packed f32x2 helpers ----
__device__ __forceinline__ ull pack2same(float x) {
    ull r; asm("mov.b64 %0, {%1, %1};" : "=l"(r) : "f"(x)); return r;
}
__device__ __forceinline__ void unpack2(ull v, float& lo, float& hi) {
    asm("mov.b64 {%0, %1}, %2;" : "=f"(lo), "=f"(hi) : "l"(v));
}
__device__ __forceinline__ ull ffma2(ull a, ull b, ull c) {
    ull d; asm("fma.rn.f32x2 %0, %1, %2, %3;" : "=l"(d) : "l"(a), "l"(b), "l"(c)); return d;
}
__device__ __forceinline__ ull fmul2(ull a, ull b) {
    ull d; asm("mul.rn.f32x2 %0, %1, %2;" : "=l"(d) : "l"(a), "l"(b)); return d;
}
__device__ __forceinline__ ull fadd2(ull a, ull b) {
    ull d; asm("add.rn.f32x2 %0, %1, %2;" : "=l"(d) : "l"(a), "l"(b)); return d;
}

// ============================================================================
// Kernel 1: V = H * P.
// Round-4 failure mode fixed: H is staged through smem with COALESCED global
// loads (row-segments contiguous), then each thread reads its quarter-row from
// smem. P read as LDS.128 (2 e-pairs per load). 4 threads/row, shfl reduce.
// ============================================================================
#define HS_STRIDE 84                    // 84 floats = 336B, 16B-aligned, low-conflict
__global__ __launch_bounds__(256) void proj_kernel(const float* __restrict__ H,
                                                   const float* __restrict__ P) {
    __shared__ __align__(16) ull   Ps[D_IN * E_DIM / 2];   // 20 KB, packed e-pairs
    __shared__ __align__(16) float Hs[64 * HS_STRIDE];     // 21 KB, one 80-d chunk of 64 rows
    {
        const ull* Pg = (const ull*)P;
        for (int i = threadIdx.x; i < D_IN * E_DIM / 2; i += 256) Ps[i] = Pg[i];
    }

    const int tid   = threadIdx.x;
    const int row_l = tid >> 2;                     // 0..63 local row
    const int seg   = tid & 3;                      // quarter-row
    const int row_base = blockIdx.x * 64;

    ull acc[8];
#pragma unroll
    for (int j = 0; j < 8; ++j) acc[j] = 0ULL;

    const float4* H4 = (const float4*)H;            // row stride = 80 float4
    for (int c = 0; c < 4; ++c) {                   // 4 chunks of 80 d's
        __syncthreads();
        // stage: 64 rows x 20 float4 (contiguous per row) = 1280 float4, 5/thread
#pragma unroll
        for (int i = 0; i < 5; ++i) {
            int idx = tid + i * 256;
            int r = idx / 20, f = idx % 20;
            float4 val = H4[(size_t)(row_base + r) * 80 + c * 20 + f];
            *(float4*)&Hs[r * HS_STRIDE + f * 4] = val;
        }
        __syncthreads();

#pragma unroll
        for (int i = 0; i < 5; ++i) {               // 5 float4 = 20 d's per thread
            float4 h = *(const float4*)&Hs[row_l * HS_STRIDE + seg * 20 + i * 4];
            const int d = c * 80 + seg * 20 + i * 4;
            ull hx = pack2same(h.x), hy = pack2same(h.y);
            ull hz = pack2same(h.z), hw = pack2same(h.w);
            const ulonglong2* p = (const ulonglong2*)&Ps[(size_t)d * 8];
#pragma unroll
            for (int j = 0; j < 4; ++j) {           // 4 LDS.128 per d-row of P
                ulonglong2 p0 = p[j], p1 = p[4 + j], p2 = p[8 + j], p3 = p[12 + j];
                ull a0 = acc[2 * j], a1 = acc[2 * j + 1];
                a0 = ffma2(p0.x, hx, a0);  a1 = ffma2(p0.y, hx, a1);
                a0 = ffma2(p1.x, hy, a0);  a1 = ffma2(p1.y, hy, a1);
                a0 = ffma2(p2.x, hz, a0);  a1 = ffma2(p2.y, hz, a1);
                a0 = ffma2(p3.x, hw, a0);  a1 = ffma2(p3.y, hw, a1);
                acc[2 * j] = a0; acc[2 * j + 1] = a1;
            }
        }
    }

    // reduce across the 4 segment lanes
#pragma unroll
    for (int j = 0; j < 8; ++j) {
        acc[j] = fadd2(acc[j], __shfl_xor_sync(0xFFFFFFFFu, acc[j], 1));
        acc[j] = fadd2(acc[j], __shfl_xor_sync(0xFFFFFFFFu, acc[j], 2));
    }
    ull* vout = (ull*)(g_V + (size_t)(row_base + row_l) * E_DIM);
    vout[2 * seg]     = acc[2 * seg];
    vout[2 * seg + 1] = acc[2 * seg + 1];
}

// ============================================================================
// Kernel 2: fused scores + argmax.  4 rows/thread (amortize LDS + argmax),
// single 512-cand chunk (KSPLIT=16), f32x2 e-pair math.
// grid = (125 row-groups, 16 ksegs) = 2000 blocks.
// ============================================================================
__device__ __forceinline__ float dot16p(ull c0, ull c1, ull c2, ull c3,
                                        ull c4, ull c5, ull c6, ull c7,
                                        const ull* __restrict__ v) {
    ull a = fmul2(c0, v[0]);
    a = ffma2(c1, v[1], a);
    a = ffma2(c2, v[2], a);
    a = ffma2(c3, v[3], a);
    a = ffma2(c4, v[4], a);
    a = ffma2(c5, v[5], a);
    a = ffma2(c6, v[6], a);
    a = ffma2(c7, v[7], a);
    float lo, hi; unpack2(a, lo, hi);
    return lo + hi;
}

__global__ __launch_bounds__(T2) void score_kernel(const float* __restrict__ CB) {
    __shared__ __align__(16) ull cb_s[KSEG * 8];        // 32 KB
    __shared__ float  red_v[8][ROWS_PB];                // 4 KB
    __shared__ int    red_i[8][ROWS_PB];                // 4 KB

    const int tid  = threadIdx.x;
    const int lane = tid & 31;
    const int warp = tid >> 5;
    const int row_base = blockIdx.x * ROWS_PB;
    const int kseg = blockIdx.y;

    // 4 row vectors per thread: rows row_base + lane + rr*32
    ull v[4][8];
#pragma unroll
    for (int rr = 0; rr < 4; ++rr) {
        const ulonglong2* Vg = (const ulonglong2*)(g_V + (size_t)(row_base + lane + rr * 32) * E_DIM);
#pragma unroll
        for (int j = 0; j < 4; ++j) {
            ulonglong2 a = Vg[j]; v[rr][2 * j] = a.x; v[rr][2 * j + 1] = a.y;
        }
    }

    // stage chunk: 512 cands * 64 B = 2048 float4, 8/thread
    {
        const float4* src = (const float4*)CB + (size_t)kseg * KSEG * 4;
        float4* dst = (float4*)cb_s;
#pragma unroll
        for (int i = 0; i < (KSEG * 4) / T2; ++i)
            dst[tid + i * T2] = src[tid + i * T2];
    }
    __syncthreads();

    float best[4]; int bi[4];
#pragma unroll
    for (int rr = 0; rr < 4; ++rr) { best[rr] = __int_as_float(0xff800000); bi[rr] = 0; }

    const int jbase = warp * (KSEG / 8);                // 64-cand stripe / warp
    const int kbase = kseg * KSEG + jbase;
#pragma unroll 2
    for (int j = 0; j < KSEG / 8; ++j) {
        const ulonglong2* q = (const ulonglong2*)(cb_s + (size_t)(jbase + j) * 8);
        ulonglong2 t0 = q[0], t1 = q[1], t2 = q[2], t3 = q[3];
        const int k = kbase + j;
#pragma unroll
        for (int rr = 0; rr < 4; ++rr) {
            float s = dot16p(t0.x, t0.y, t1.x, t1.y, t2.x, t2.y, t3.x, t3.y, v[rr]);
            if (s > best[rr]) { best[rr] = s; bi[rr] = k; }   // strict > == first-max
        }
    }

    // cross-warp reduce (warps hold disjoint ascending k-stripes of the same 128 rows)
#pragma unroll
    for (int rr = 0; rr < 4; ++rr) {
        red_v[warp][lane + rr * 32] = best[rr];
        red_i[warp][lane + rr * 32] = bi[rr];
    }
    __syncthreads();
    if (tid < ROWS_PB) {
        float bv = red_v[0][tid]; int b = red_i[0][tid];
#pragma unroll
        for (int w = 1; w < 8; ++w) {
            float vv = red_v[w][tid]; int i = red_i[w][tid];
            if (vv > bv || (vv == bv && i < b)) { bv = vv; b = i; }
        }
        g_pv[(size_t)kseg * B_T + row_base + tid] = bv;
        g_pi[(size_t)kseg * B_T + row_base + tid] = b;
    }
}

// ============================================================================
// Kernel 3: combine KSPLIT partials; label written as float VALUE (output
// buffer is float32 — int bit patterns read as denormals).
// ============================================================================
__global__ __launch_bounds__(256) void combine_kernel(float* __restrict__ out) {
    int row = blockIdx.x * 256 + threadIdx.x;
    if (row >= B_T) return;
    float bv = g_pv[row];
    int   bi = g_pi[row];
#pragma unroll
    for (int s = 1; s < KSPLIT; ++s) {
        float v = g_pv[(size_t)s * B_T + row];
        int   i = g_pi[(size_t)s * B_T + row];
        if (v > bv || (v == bv && i < bi)) { bv = v; bi = i; }
    }
    out[row] = (float)bi;
}

// ============================================================================
extern "C" void kernel_launch(void* const* d_in, const int* in_sizes, int n_in,
                              void* d_out, int out_size) {
    // Input dispatch by element count (ordering-proof):
    //   H = 5,120,000 ; P = 5,120 ; CB = 131,072
    const float* H  = nullptr;
    const float* P  = nullptr;
    const float* CB = nullptr;
    for (int i = 0; i < n_in; ++i) {
        if      (in_sizes[i] == B_T * D_IN)   H  = (const float*)d_in[i];
        else if (in_sizes[i] == D_IN * E_DIM) P  = (const float*)d_in[i];
        else if (in_sizes[i] == K_CB * E_DIM) CB = (const float*)d_in[i];
    }
    if (!H)  H  = (const float*)d_in[0];
    if (!P)  P  = (const float*)d_in[1];
    if (!CB) CB = (const float*)d_in[2];

    float* out = (float*)d_out;

    proj_kernel<<<B_T / 64, 256>>>(H, P);
    score_kernel<<<dim3(NBLK_ROWS, KSPLIT), T2>>>(CB);
    combine_kernel<<<(B_T + 255) / 256, 256>>>(out);
}